// round 5
// baseline (speedup 1.0000x reference)
#include <cuda_runtime.h>
#include <math.h>
#include <stdint.h>

#define B_  128
#define T_  1024
#define NX_ 256
#define NH_ 512
#define NY_ 256

// ---------------------------------------------------------------------------
// Generic NT SGEMM: C[m][n] = sum_k A[m][k] * B[n][k]   (unchanged, proven)
// ---------------------------------------------------------------------------
template <int BM, int BN, int BK, int TM, int TN, int NT>
__global__ __launch_bounds__(NT) void sgemm_nt(
    const float* __restrict__ A,
    const float* __restrict__ Bm,
    float* __restrict__ C,
    int M, int N, int K)
{
    __shared__ float As[BK][BM];
    __shared__ float Bs[BK][BN];

    const int tid = threadIdx.x;
    const int m0 = blockIdx.y * BM;
    const int n0 = blockIdx.x * BN;
    const int tx = tid % (BN / TN);
    const int ty = tid / (BN / TN);

    float acc[TM][TN];
#pragma unroll
    for (int i = 0; i < TM; i++)
#pragma unroll
        for (int j = 0; j < TN; j++) acc[i][j] = 0.0f;

    for (int k0 = 0; k0 < K; k0 += BK) {
#pragma unroll
        for (int i = tid; i < BM * (BK / 4); i += NT) {
            int m = i / (BK / 4);
            int kq = (i % (BK / 4)) * 4;
            float4 v = *(const float4*)(A + (long)(m0 + m) * K + k0 + kq);
            As[kq + 0][m] = v.x;
            As[kq + 1][m] = v.y;
            As[kq + 2][m] = v.z;
            As[kq + 3][m] = v.w;
        }
#pragma unroll
        for (int i = tid; i < BN * (BK / 4); i += NT) {
            int n = i / (BK / 4);
            int kq = (i % (BK / 4)) * 4;
            float4 v = *(const float4*)(Bm + (long)(n0 + n) * K + k0 + kq);
            Bs[kq + 0][n] = v.x;
            Bs[kq + 1][n] = v.y;
            Bs[kq + 2][n] = v.z;
            Bs[kq + 3][n] = v.w;
        }
        __syncthreads();

#pragma unroll
        for (int k = 0; k < BK; ++k) {
            float a[TM], b[TN];
#pragma unroll
            for (int i = 0; i < TM; i++) a[i] = As[k][ty * TM + i];
#pragma unroll
            for (int j = 0; j < TN; j++) b[j] = Bs[k][tx * TN + j];
#pragma unroll
            for (int i = 0; i < TM; i++)
#pragma unroll
                for (int j = 0; j < TN; j++) acc[i][j] = fmaf(a[i], b[j], acc[i][j]);
        }
        __syncthreads();
    }

#pragma unroll
    for (int i = 0; i < TM; i++) {
        float4 v = make_float4(acc[i][0], acc[i][1], acc[i][2], acc[i][3]);
        *(float4*)(C + (long)(m0 + ty * TM + i) * N + n0 + tx * TN) = v;
    }
}

// No-op kernel: shifts ncu's fixed capture index (-s 5) onto the RNN kernel
// (4 launches per call, RNN at position 1 -> launch 5 = RNN of 2nd call).
__global__ void knoop() {}

// ---------------------------------------------------------------------------
// Sequential recurrence: cluster-of-8, TWO ping-ponged batch groups per CTA.
//
// 16 clusters x 8 CTAs (full chip). Cluster -> 8 batches, split into groups
// g=0 (first 4) and g=1 (last 4). Rank jt owns 64 output columns.
// Per time step, each CTA processes group 0 then group 1; group g's DSMEM
// exchange + mbarrier wait overlaps with group g^1's compute.
// h per group double-buffered in SMEM: hTg[g][s][k][b4] (2048 floats each).
// Exchange: 7x cp.async.bulk (1KB) signaling destination full[g][s2] barrier.
// ---------------------------------------------------------------------------
#define CL   8
#define JT   64
#define GB   4            // batches per group
#define NTHR 512

#define HT1       (NH_ * GB)                 // 2048 floats per h buffer
#define WHT_OFF   0                          // whT[k][jloc]: 512 x 64 = 32768
#define HT_OFF    (NH_ * JT)                 // 32768
#define RED_OFF   (HT_OFF + 4 * HT1)         // 40960 : red[w][j*5+b], 16 x 320
#define MBAR_OFF  (RED_OFF + 16 * 320)       // 46080
#define SMEM_FLOATS (MBAR_OFF + 8)           // 4 mbarriers = 32B (+pad)
#define SMEM_BYTES  (SMEM_FLOATS * 4)        // 184352

#define CHUNK_BYTES   (JT * GB * 4)            // 1024
#define EXPECT_BYTES  ((CL - 1) * CHUNK_BYTES) // 7168

// ---- PTX helpers ----
__device__ __forceinline__ uint32_t smem_u32(const void* p)
{
    uint32_t a;
    asm("{ .reg .u64 t; cvta.to.shared.u64 t, %1; cvt.u32.u64 %0, t; }"
        : "=r"(a) : "l"(p));
    return a;
}
__device__ __forceinline__ uint32_t mapa_rank(uint32_t addr, uint32_t rank)
{
    uint32_t r;
    asm("mapa.shared::cluster.u32 %0, %1, %2;" : "=r"(r) : "r"(addr), "r"(rank));
    return r;
}
__device__ __forceinline__ unsigned long long pack2(float x)
{
    unsigned long long r;
    asm("mov.b64 %0, {%1, %1};" : "=l"(r) : "f"(x));
    return r;
}
__device__ __forceinline__ void unpack2(unsigned long long v, float& lo, float& hi)
{
    asm("mov.b64 {%0, %1}, %2;" : "=f"(lo), "=f"(hi) : "l"(v));
}
__device__ __forceinline__ void ffma2(unsigned long long& d,
                                      unsigned long long a, unsigned long long b)
{
    asm("fma.rn.f32x2 %0, %1, %2, %0;" : "+l"(d) : "l"(a), "l"(b));
}

#define MBAR_INIT(a, n) \
    asm volatile("mbarrier.init.shared.b64 [%0], %1;" :: "r"(a), "r"(n) : "memory")
#define MBAR_EXPECT_TX(a, bytes) \
    asm volatile("mbarrier.arrive.expect_tx.shared.b64 _, [%0], %1;" \
                 :: "r"(a), "r"(bytes) : "memory")

#define MBAR_WAIT_PARITY_CL(mbar, parity) do {                                  \
    asm volatile(                                                               \
        "{\n\t"                                                                 \
        ".reg .pred P1;\n\t"                                                    \
        "WL_%=:\n\t"                                                            \
        "mbarrier.try_wait.parity.acquire.cluster.shared::cta.b64 P1, [%0], %1, 0x989680;\n\t" \
        "@P1 bra.uni WD_%=;\n\t"                                                \
        "bra.uni WL_%=;\n\t"                                                    \
        "WD_%=:\n\t"                                                            \
        "}"                                                                     \
        :: "r"(mbar), "r"(parity) : "memory");                                  \
} while (0)

__global__ __launch_bounds__(NTHR, 1) __cluster_dims__(CL, 1, 1)
void rnn_seq_pp(const float* __restrict__ Wh,
                const float* __restrict__ h0,
                float* __restrict__ hs)
{
    extern __shared__ float sm[];
    float* whT = sm + WHT_OFF;
    float* hTg = sm + HT_OFF;     // [g*2+s][k*4+b]
    float* red = sm + RED_OFF;    // [w][j*5+b]

    const int tid  = threadIdx.x;
    const int wid  = tid >> 5;
    const int lane = tid & 31;

    const int jt  = blockIdx.x & (CL - 1);
    const int bt  = blockIdx.x / CL;
    const int b0g = bt * 8;          // 8 batches per cluster (2 groups of 4)
    const int j0g = jt * JT;

    const uint32_t smem_base = smem_u32(sm);
    const uint32_t mbar_base = smem_base + MBAR_OFF * 4;
    // barrier (g,s) at mbar_base + (g*2+s)*8

    // Resident Wh tile, transposed: whT[k][jloc]
    for (int i = tid; i < JT * (NH_ / 4); i += NTHR) {
        int jl = i / (NH_ / 4);
        int k4 = (i % (NH_ / 4)) * 4;
        float4 v = *(const float4*)(Wh + (size_t)(j0g + jl) * NH_ + k4);
        whT[(k4 + 0) * JT + jl] = v.x;
        whT[(k4 + 1) * JT + jl] = v.y;
        whT[(k4 + 2) * JT + jl] = v.z;
        whT[(k4 + 3) * JT + jl] = v.w;
    }
    // Preload buffer 0 of each group with h0: hTg[g][0][k*4+b]
#pragma unroll
    for (int g = 0; g < 2; g++) {
        float* dst = hTg + (g * 2 + 0) * HT1;
        for (int i = tid; i < HT1; i += NTHR) {
            int k = i >> 2, b = i & 3;
            dst[i] = h0[(size_t)(b0g + g * 4 + b) * NH_ + k];
        }
    }
    if (tid == 0) {
#pragma unroll
        for (int gs = 0; gs < 4; gs++) {
            MBAR_INIT(mbar_base + gs * 8, 1);
            MBAR_EXPECT_TX(mbar_base + gs * 8, EXPECT_BYTES);
        }
    }
    __syncthreads();
    asm volatile("barrier.cluster.arrive.aligned;" ::: "memory");
    asm volatile("barrier.cluster.wait.aligned;" ::: "memory");

    // Compute mapping: 16 warps k-split (32 each); lane tile = 1b x 8j (FFMA2)
    const int jg8 = (lane & 7) * 8;     // 8 j-groups
    const int bgl = lane >> 3;          // 0..3 : this lane's batch (within group)
    const int kw0 = wid * 32;
    const int grot = lane & 7;          // rotation for conflict-free partial stores

    // Epilogue mapping (tid < 256): one output per thread
    const int ej = tid & 63;            // local j
    const int ebl = (tid >> 6) & 3;     // local b (within group)

    int ph[4] = {0, 0, 0, 0};           // parity per (g,s)

    for (int t = 0; t < T_; ++t) {
        const int s  = t & 1;
        const int s2 = s ^ 1;

#pragma unroll
        for (int g = 0; g < 2; g++) {
            const float* htc = hTg + (g * 2 + s) * HT1;
            const int gs_cur = g * 2 + s;
            const int gs_nxt = g * 2 + s2;

            // Prefetch pre-activation before the wait (DRAM latency overlap)
            float pre = 0.0f;
            if (tid < 256)
                pre = __ldcg(hs + ((size_t)(b0g + g * 4 + ebl) * T_ + t) * NH_
                             + j0g + ej);

            if (t > 0) {
                const uint32_t mb = mbar_base + gs_cur * 8;
                MBAR_WAIT_PARITY_CL(mb, ph[gs_cur]);
                ph[gs_cur] ^= 1;
                if (tid == 0 && t + 2 < T_) MBAR_EXPECT_TX(mb, EXPECT_BYTES);
            }

            unsigned long long acc[4];
#pragma unroll
            for (int p = 0; p < 4; p++) acc[p] = 0ull;

#pragma unroll 8
            for (int k = kw0; k < kw0 + 32; ++k) {
                unsigned long long a = pack2(htc[k * 4 + bgl]);
                ulonglong2 W0 = *(const ulonglong2*)(whT + k * JT + jg8);
                ulonglong2 W1 = *(const ulonglong2*)(whT + k * JT + jg8 + 4);
                ffma2(acc[0], a, W0.x);
                ffma2(acc[1], a, W0.y);
                ffma2(acc[2], a, W1.x);
                ffma2(acc[3], a, W1.y);
            }

            // Unpack & store partials, rotated order for conflict-free banks:
            // red[wid][ (jg8+jj)*5 + bgl ], jj = (m + grot) & 7
            float av[8];
#pragma unroll
            for (int p = 0; p < 4; p++) unpack2(acc[p], av[2 * p], av[2 * p + 1]);
#pragma unroll
            for (int m = 0; m < 8; m++) {
                int jj = (m + grot) & 7;
                red[wid * 320 + (jg8 + jj) * 5 + bgl] = av[jj];
            }
            __syncthreads();

            if (tid < 256) {
                float sacc = pre;
#pragma unroll
                for (int w = 0; w < 16; w++) sacc += red[w * 320 + ej * 5 + ebl];
                float hv = tanhf(sacc);
                hs[((size_t)(b0g + g * 4 + ebl) * T_ + t) * NH_ + j0g + ej] = hv;
                // local write into next buffer: hTg[g][s2][(j0g+ej)*4 + ebl]
                hTg[gs_nxt * HT1 + (j0g + ej) * 4 + ebl] = hv;
            }
            __syncthreads();

            // Push own 1KB chunk to the 7 peers, signal their full[g][s2].
            if (t < T_ - 1 && tid < CL && tid != jt) {
                asm volatile("fence.proxy.async.shared::cta;" ::: "memory");
                uint32_t src = smem_base +
                    (uint32_t)(HT_OFF + gs_nxt * HT1 + j0g * 4) * 4u;
                uint32_t dst = mapa_rank(src, (uint32_t)tid);
                uint32_t mb  = mapa_rank(mbar_base + gs_nxt * 8, (uint32_t)tid);
                asm volatile(
                    "cp.async.bulk.shared::cluster.shared::cta.mbarrier::complete_tx::bytes "
                    "[%0], [%1], %2, [%3];"
                    :: "r"(dst), "r"(src), "r"(CHUNK_BYTES), "r"(mb) : "memory");
            }
        }
    }

    asm volatile("barrier.cluster.arrive.aligned;" ::: "memory");
    asm volatile("barrier.cluster.wait.aligned;" ::: "memory");
}

// ---------------------------------------------------------------------------
// Launch
// ---------------------------------------------------------------------------
extern "C" void kernel_launch(void* const* d_in, const int* in_sizes, int n_in,
                              void* d_out, int out_size)
{
    const float* x  = (const float*)d_in[0];
    const float* h0 = (const float*)d_in[1];
    const float* Wi = (const float*)d_in[2];
    const float* Wh = (const float*)d_in[3];
    const float* Wy = (const float*)d_in[4];

    float* y  = (float*)d_out;
    float* hs = y + (size_t)B_ * T_ * NY_;

    // Phase 1: pre = x @ Wi^T  -> hs region (scratch)
    {
        dim3 grid(NH_ / 64, (B_ * T_) / 128);
        sgemm_nt<128, 64, 16, 8, 4, 256><<<grid, 256>>>(x, Wi, hs, B_ * T_, NH_, NX_);
    }
    // Phase 2: sequential recurrence (ping-ponged groups)
    {
        cudaFuncSetAttribute(rnn_seq_pp,
                             cudaFuncAttributeMaxDynamicSharedMemorySize, SMEM_BYTES);
        rnn_seq_pp<<<128, NTHR, SMEM_BYTES>>>(Wh, h0, hs);
    }
    // Phase 3: y = hs @ Wy^T
    {
        dim3 grid(NY_ / 64, (B_ * T_) / 128);
        sgemm_nt<128, 64, 16, 8, 4, 256><<<grid, 256>>>(hs, Wy, y, B_ * T_, NY_, NH_);
    }
    // Launch-count shim so ncu (-s 5) captures the RNN kernel next profile.
    knoop<<<1, 1>>>();
}

// round 6
// speedup vs baseline: 2.0409x; 2.0409x over previous
#include <cuda_runtime.h>
#include <math.h>
#include <stdint.h>

#define B_  128
#define T_  1024
#define NX_ 256
#define NH_ 512
#define NY_ 256

// Persistent state (allocation-free scratch).
__device__ float g_h[2][B_ * NH_];
__device__ unsigned g_bar_count = 0;
__device__ unsigned g_bar_gen = 0;

// ---------------------------------------------------------------------------
// Generic NT SGEMM (proven): C[m][n] = sum_k A[m][k] * B[n][k]
// ---------------------------------------------------------------------------
template <int BM, int BN, int BK, int TM, int TN, int NT>
__global__ __launch_bounds__(NT) void sgemm_nt(
    const float* __restrict__ A,
    const float* __restrict__ Bm,
    float* __restrict__ C,
    int M, int N, int K)
{
    __shared__ float As[BK][BM];
    __shared__ float Bs[BK][BN];

    const int tid = threadIdx.x;
    const int m0 = blockIdx.y * BM;
    const int n0 = blockIdx.x * BN;
    const int tx = tid % (BN / TN);
    const int ty = tid / (BN / TN);

    float acc[TM][TN];
#pragma unroll
    for (int i = 0; i < TM; i++)
#pragma unroll
        for (int j = 0; j < TN; j++) acc[i][j] = 0.0f;

    for (int k0 = 0; k0 < K; k0 += BK) {
#pragma unroll
        for (int i = tid; i < BM * (BK / 4); i += NT) {
            int m = i / (BK / 4);
            int kq = (i % (BK / 4)) * 4;
            float4 v = *(const float4*)(A + (long)(m0 + m) * K + k0 + kq);
            As[kq + 0][m] = v.x;
            As[kq + 1][m] = v.y;
            As[kq + 2][m] = v.z;
            As[kq + 3][m] = v.w;
        }
#pragma unroll
        for (int i = tid; i < BN * (BK / 4); i += NT) {
            int n = i / (BK / 4);
            int kq = (i % (BK / 4)) * 4;
            float4 v = *(const float4*)(Bm + (long)(n0 + n) * K + k0 + kq);
            Bs[kq + 0][n] = v.x;
            Bs[kq + 1][n] = v.y;
            Bs[kq + 2][n] = v.z;
            Bs[kq + 3][n] = v.w;
        }
        __syncthreads();

#pragma unroll
        for (int k = 0; k < BK; ++k) {
            float a[TM], b[TN];
#pragma unroll
            for (int i = 0; i < TM; i++) a[i] = As[k][ty * TM + i];
#pragma unroll
            for (int j = 0; j < TN; j++) b[j] = Bs[k][tx * TN + j];
#pragma unroll
            for (int i = 0; i < TM; i++)
#pragma unroll
                for (int j = 0; j < TN; j++) acc[i][j] = fmaf(a[i], b[j], acc[i][j]);
        }
        __syncthreads();
    }

#pragma unroll
    for (int i = 0; i < TM; i++) {
        float4 v = make_float4(acc[i][0], acc[i][1], acc[i][2], acc[i][3]);
        *(float4*)(C + (long)(m0 + ty * TM + i) * N + n0 + tx * TN) = v;
    }
}

// ---------------------------------------------------------------------------
// FFMA2 helpers
// ---------------------------------------------------------------------------
__device__ __forceinline__ void ffma2(unsigned long long& d,
                                      unsigned long long a, unsigned long long b)
{
    asm("fma.rn.f32x2 %0, %1, %2, %0;" : "+l"(d) : "l"(a), "l"(b));
}
__device__ __forceinline__ void unpack2(unsigned long long v, float& lo, float& hi)
{
    asm("mov.b64 {%0, %1}, %2;" : "=f"(lo), "=f"(hi) : "l"(v));
}

// ---------------------------------------------------------------------------
// Persistent fused kernel: recurrence (global-barrier, FFMA2) + y-GEMM tail.
// 128 CTAs = 8 b-tiles(16) x 16 j-tiles(32). 256 threads.
// SMEM: whT[512][32] (64KB) | hTd[512][32] dup-pairs (64KB) | red[8][512] (16KB)
// Tail reuses smem: hsS[64][65], wyS[64][20].
// ---------------------------------------------------------------------------
#define SEQ_NBLK 128
#define NTHR     256

#define WHT_OFF 0
#define HTD_OFF 16384
#define RED_OFF 32768
#define SMEM_FLOATS (RED_OFF + 8 * 512)
#define SMEM_BYTES  (SMEM_FLOATS * 4)   // 147456

__device__ __forceinline__ void grid_sync_all(int t)
{
    __threadfence();
    __syncthreads();
    if (threadIdx.x == 0) {
        volatile unsigned* genp = &g_bar_gen;
        unsigned gen = *genp;
        unsigned c = atomicAdd(&g_bar_count, 1u);
        if (c == SEQ_NBLK - 1) {
            g_bar_count = 0;
            __threadfence();
            atomicExch(&g_bar_gen, gen + 1);
        } else {
            // Backoff poll: avoid LTS serialization at the release line.
            while (*genp == gen) { __nanosleep(128); }
        }
    }
    __syncthreads();
}

__global__ __launch_bounds__(NTHR, 1) void rnn_fused(
    const float* __restrict__ Wh,   // [NH][NH]
    const float* __restrict__ h0,   // [B][NH]
    const float* __restrict__ Wy,   // [NY][NH]
    float* __restrict__ hs,         // [B][T][NH] (pre in, h out in place)
    float* __restrict__ y)          // [B][T][NY]
{
    extern __shared__ float sm[];
    float* whT = sm + WHT_OFF;   // [k][j]   stride 32
    float* hTd = sm + HTD_OFF;   // [k][b*2] stride 32, duplicated pairs
    float* red = sm + RED_OFF;   // [w][b*32+j]

    const int tid  = threadIdx.x;
    const int wid  = tid >> 5;
    const int lane = tid & 31;

    const int jt  = blockIdx.x & 15;
    const int bt  = blockIdx.x >> 4;
    const int j0g = jt * 32;
    const int b0g = bt * 16;

    // ---- resident Wh tile, transposed: whT[k][j] ----
    for (int i = tid; i < 32 * 128; i += NTHR) {
        int j  = i >> 7;
        int kq = (i & 127) * 4;
        float4 v = *(const float4*)(Wh + (size_t)(j0g + j) * NH_ + kq);
        whT[(kq + 0) * 32 + j] = v.x;
        whT[(kq + 1) * 32 + j] = v.y;
        whT[(kq + 2) * 32 + j] = v.z;
        whT[(kq + 3) * 32 + j] = v.w;
    }
    __syncthreads();

    // compute mapping: 8 warps k-split 64 each; lane tile = 4b x 4j (2 pairs)
    const int bg  = lane >> 3;     // b group: batches bg*4..+3
    const int jg  = lane & 7;      // j group: cols jg*4..+3
    const int kw0 = wid * 64;

    // reload mapping: lane -> b = lane&15 (bank-conflict-free stores)
    const int rb   = lane & 15;
    const int rhalf= lane >> 4;

    for (int t = 0; t < T_; ++t) {
        const float* hin = (t == 0) ? h0 : (const float*)g_h[t & 1];
        float* hout      = g_h[(t + 1) & 1];

        // prefetch pre-activations (2 per thread), consumed ~2k cyc later
        const int oo0 = tid, oo1 = tid + 256;
        float pre0 = __ldcg(hs + ((size_t)(b0g + (oo0 >> 5)) * T_ + t) * NH_ + j0g + (oo0 & 31));
        float pre1 = __ldcg(hs + ((size_t)(b0g + (oo1 >> 5)) * T_ + t) * NH_ + j0g + (oo1 & 31));

        // ---- reload h as duplicated pairs: hTd[k][b*2{,+1}] = h[b][k] ----
        // per thread: 8 float4 loads of batch rb; stores hit 16 distinct banks.
#pragma unroll
        for (int q = 0; q < 8; ++q) {
            int kq = (wid * 16 + rhalf * 8 + q) * 4;
            float4 v = __ldcg((const float4*)(hin + (size_t)(b0g + rb) * NH_ + kq));
            float2* d0 = (float2*)&hTd[(kq + 0) * 32 + rb * 2];
            float2* d1 = (float2*)&hTd[(kq + 1) * 32 + rb * 2];
            float2* d2 = (float2*)&hTd[(kq + 2) * 32 + rb * 2];
            float2* d3 = (float2*)&hTd[(kq + 3) * 32 + rb * 2];
            *d0 = make_float2(v.x, v.x);
            *d1 = make_float2(v.y, v.y);
            *d2 = make_float2(v.z, v.z);
            *d3 = make_float2(v.w, v.w);
        }
        __syncthreads();

        // ---- FFMA2 k-loop: 8 FFMA2 + 3 LDS.128 per k ----
        unsigned long long acc[4][2];
#pragma unroll
        for (int i = 0; i < 4; i++) { acc[i][0] = 0ull; acc[i][1] = 0ull; }

#pragma unroll 8
        for (int k = kw0; k < kw0 + 64; ++k) {
            ulonglong2 alo = *(const ulonglong2*)&hTd[k * 32 + bg * 8];      // (b0,b0,b1,b1)
            ulonglong2 ahi = *(const ulonglong2*)&hTd[k * 32 + bg * 8 + 4];  // (b2,b2,b3,b3)
            ulonglong2 w   = *(const ulonglong2*)&whT[k * 32 + jg * 4];      // (j0,j1,j2,j3)
            ffma2(acc[0][0], alo.x, w.x); ffma2(acc[0][1], alo.x, w.y);
            ffma2(acc[1][0], alo.y, w.x); ffma2(acc[1][1], alo.y, w.y);
            ffma2(acc[2][0], ahi.x, w.x); ffma2(acc[2][1], ahi.x, w.y);
            ffma2(acc[3][0], ahi.y, w.x); ffma2(acc[3][1], ahi.y, w.y);
        }

        // ---- stash partials: red[wid][(bg*4+i)*32 + jg*4 + 2p] (u64) ----
#pragma unroll
        for (int i = 0; i < 4; i++) {
            *(unsigned long long*)&red[wid * 512 + (bg * 4 + i) * 32 + jg * 4]     = acc[i][0];
            *(unsigned long long*)&red[wid * 512 + (bg * 4 + i) * 32 + jg * 4 + 2] = acc[i][1];
        }
        __syncthreads();

        // ---- reduce 8 warps + pre, tanh, publish ----
        {
            float s0 = pre0, s1 = pre1;
#pragma unroll
            for (int w = 0; w < 8; w++) {
                s0 += red[w * 512 + oo0];
                s1 += red[w * 512 + oo1];
            }
            float hv0 = tanhf(s0);
            float hv1 = tanhf(s1);
            int b0 = oo0 >> 5, j0 = oo0 & 31;
            int b1 = oo1 >> 5, j1 = oo1 & 31;
            hs[((size_t)(b0g + b0) * T_ + t) * NH_ + j0g + j0] = hv0;
            hs[((size_t)(b0g + b1) * T_ + t) * NH_ + j0g + j1] = hv1;
            hout[(size_t)(b0g + b0) * NH_ + j0g + j0] = hv0;
            hout[(size_t)(b0g + b1) * NH_ + j0g + j1] = hv1;
        }

        grid_sync_all(t);
    }

    // =======================================================================
    // Tail: y = hs @ Wy^T for this CTA's slice (b: b0g..+16, y: jt*16..+16)
    // hsS[k][m] stride 65, wyS[k][yy] stride 20 (16B-aligned float4 rows).
    // =======================================================================
    {
        float* hsS = sm;             // 64 x 65
        float* wyS = sm + 64 * 65;   // 64 x 20
        const int y0 = jt * 16;
        const int m  = tid & 63;
        const int cg = tid >> 6;     // col group: cols cg*4..+3

        // wy load mapping (conflict-free stores): yy = tid&15, kq8 = tid>>4
        const int wyy = tid & 15;
        const int wkq = (tid >> 4) * 4;

        __syncthreads();

        for (int mt = 0; mt < 256; ++mt) {
            float a0 = 0.f, a1 = 0.f, a2 = 0.f, a3 = 0.f;

            for (int kb = 0; kb < 8; ++kb) {
                // hs tile: 64 rows x 64 k, transposed into hsS[k][m]
#pragma unroll
                for (int q = 0; q < 4; ++q) {
                    int idx = tid + q * 256;           // 0..1023
                    int mm = idx >> 4;
                    int kq = (idx & 15) * 4;
                    int r  = mt * 64 + mm;
                    const float* src = hs + ((size_t)(b0g + (r >> 10)) * T_ + (r & 1023)) * NH_
                                          + kb * 64 + kq;
                    float4 v = __ldcg((const float4*)src);
                    hsS[(kq + 0) * 65 + mm] = v.x;
                    hsS[(kq + 1) * 65 + mm] = v.y;
                    hsS[(kq + 2) * 65 + mm] = v.z;
                    hsS[(kq + 3) * 65 + mm] = v.w;
                }
                // Wy tile: 16 y x 64 k into wyS[k][yy]
                {
                    float4 v = *(const float4*)(Wy + (size_t)(y0 + wyy) * NH_ + kb * 64 + wkq);
                    wyS[(wkq + 0) * 20 + wyy] = v.x;
                    wyS[(wkq + 1) * 20 + wyy] = v.y;
                    wyS[(wkq + 2) * 20 + wyy] = v.z;
                    wyS[(wkq + 3) * 20 + wyy] = v.w;
                }
                __syncthreads();

#pragma unroll 16
                for (int k = 0; k < 64; ++k) {
                    float a = hsS[k * 65 + m];
                    float4 w = *(const float4*)&wyS[k * 20 + cg * 4];
                    a0 = fmaf(a, w.x, a0);
                    a1 = fmaf(a, w.y, a1);
                    a2 = fmaf(a, w.z, a2);
                    a3 = fmaf(a, w.w, a3);
                }
                __syncthreads();
            }

            int r = mt * 64 + m;
            float4 out = make_float4(a0, a1, a2, a3);
            *(float4*)(y + ((size_t)(b0g + (r >> 10)) * T_ + (r & 1023)) * NY_ + y0 + cg * 4) = out;
        }
    }
}

// ---------------------------------------------------------------------------
// Launch: [sgemm(pre), rnn_fused]. Last launch = rnn_fused -> ncu captures it.
// ---------------------------------------------------------------------------
extern "C" void kernel_launch(void* const* d_in, const int* in_sizes, int n_in,
                              void* d_out, int out_size)
{
    const float* x  = (const float*)d_in[0];
    const float* h0 = (const float*)d_in[1];
    const float* Wi = (const float*)d_in[2];
    const float* Wh = (const float*)d_in[3];
    const float* Wy = (const float*)d_in[4];

    float* y  = (float*)d_out;
    float* hs = y + (size_t)B_ * T_ * NY_;

    // Phase 1: pre = x @ Wi^T -> hs region (scratch)
    {
        dim3 grid(NH_ / 64, (B_ * T_) / 128);
        sgemm_nt<128, 64, 16, 8, 4, 256><<<grid, 256>>>(x, Wi, hs, B_ * T_, NH_, NX_);
    }
    // Phase 2+3 fused: recurrence + y GEMM tail (persistent, 128 CTAs)
    {
        cudaFuncSetAttribute(rnn_fused,
                             cudaFuncAttributeMaxDynamicSharedMemorySize, SMEM_BYTES);
        rnn_fused<<<SEQ_NBLK, NTHR, SMEM_BYTES>>>(Wh, h0, Wy, hs, y);
    }
}